// round 7
// baseline (speedup 1.0000x reference)
#include <cuda_runtime.h>
#include <cstdint>
#include <math.h>

// NT_Xent collapsed: neg_n = (r_n/||r_n||) . S / T,  S = sum_m mem_m/||mem_m||.
// One persistent kernel, grid = 148 x 1024 (all blocks co-resident).
// Phase 1: lane-local cp.async pipeline (3-stage, 16KB tiles) streams the 32MB
//          bank through smem; each thread copies exactly the slot it consumes
//          -> no barriers needed inside the pipeline.
// ALL block-local scratch is overlaid on the 48KB dynamic stage buffer so
// static smem is 0 (static+dynamic must fit 48KB opt-out cap; we also opt in
// via cudaFuncSetAttribute in kernel_launch — no graph node, capture-safe).
// grid-sync; Phase 2: every block rebuilds S, computes loss rows; the
// last-arriving block reduces losses -> mean -> out, resets counters.
// All reductions are fixed-order trees -> deterministic.

#define D        128
#define DV       32              // float4 per row
#define GRID     148
#define T        1024
#define NW       32
#define TILE_R   32              // rows per tile
#define TILE_V4  (TILE_R * DV)   // 1024 float4 = 16KB
#define NSTAGE   3
#define PRE      2
#define SMEM_BYTES (NSTAGE * TILE_V4 * 16)   // 49152
#define INV_T    10.0f
#define EPSN     1e-8f
#define EPS2     (1e-8f * 1e-8f)

__device__ float        g_partialS[GRID * D];
__device__ float        g_partialLoss[GRID];
__device__ unsigned int g_cnt1 = 0;
__device__ unsigned int g_cnt2 = 0;

__device__ __forceinline__ float warp_sum(float v) {
    #pragma unroll
    for (int o = 16; o > 0; o >>= 1) v += __shfl_xor_sync(0xffffffffu, v, o);
    return v;
}
__device__ __forceinline__ float dot4(float4 a, float4 b) {
    return a.x * b.x + a.y * b.y + a.z * b.z + a.w * b.w;
}
__device__ __forceinline__ void cp16(unsigned int saddr, const float4* g) {
    asm volatile("cp.async.cg.shared.global [%0], [%1], 16;" :: "r"(saddr), "l"(g));
}
#define CP_COMMIT() asm volatile("cp.async.commit_group;" ::: "memory")

__global__ __launch_bounds__(T, 1)
void fused_ntxent_kernel(const float4* __restrict__ mem, int M,
                         const float4* __restrict__ real,
                         const float4* __restrict__ pert, int N,
                         float* __restrict__ out) {
    extern __shared__ float4 stages[];           // 49152 B dynamic, overlaid below

    // Overlays (used only AFTER the pipeline fully drains):
    float4* sacc   = stages;                     // [NW*32]  16KB  @ 0
    float*  Sq     = (float*)(stages + NW * 32); // [8*D]     4KB  @ 16KB
    float*  S      = Sq + 8 * D;                 // [D]      512B
    float*  wsum   = S + D;                      // [NW]     128B
    int*    islast = (int*)(wsum + NW);          // [1]

    const int tid  = threadIdx.x;
    const int w    = tid >> 5;
    const int lane = tid & 31;
    const int bid  = blockIdx.x;
    const int gw   = bid * NW + w;

    // ================= Phase 1: lane-local cp.async pipeline =================
    const int NTILES = M / TILE_R;
    const int cnt    = (NTILES - bid + GRID - 1) / GRID;   // tiles for this block
    const unsigned int sbase =
        (unsigned int)__cvta_generic_to_shared(stages) + (unsigned int)tid * 16u;

    #pragma unroll
    for (int p = 0; p < PRE; p++) {
        int t = bid + p * GRID;
        if (t < NTILES)
            cp16(sbase + (unsigned int)(p * TILE_V4) * 16u,
                 mem + (size_t)t * TILE_V4 + tid);
        CP_COMMIT();
    }

    float4 acc = make_float4(0.f, 0.f, 0.f, 0.f);
    #pragma unroll 1
    for (int k = 0; k < cnt; k++) {
        asm volatile("cp.async.wait_group %0;" :: "n"(PRE - 1) : "memory");
        // consume this thread's own slot of stage k%NSTAGE (self-copied -> visible)
        float4 v = stages[(k % NSTAGE) * TILE_V4 + tid];
        float  s = warp_sum(dot4(v, v));
        float inv = rsqrtf(fmaxf(s, EPS2));      // == 1/max(sqrt(s),EPS)
        acc.x += v.x * inv;  acc.y += v.y * inv;
        acc.z += v.z * inv;  acc.w += v.w * inv;
        // refill
        int t = bid + (k + PRE) * GRID;
        if (t < NTILES)
            cp16(sbase + (unsigned int)(((k + PRE) % NSTAGE) * TILE_V4) * 16u,
                 mem + (size_t)t * TILE_V4 + tid);
        CP_COMMIT();
    }
    asm volatile("cp.async.wait_group 0;" ::: "memory");

    // tail rows (M % TILE_R), one per global warp, direct LDG
    {
        int r = NTILES * TILE_R + gw;
        if (r < M) {
            float4 v = mem[(size_t)r * DV + lane];
            float  s = warp_sum(dot4(v, v));
            float inv = rsqrtf(fmaxf(s, EPS2));
            acc.x += v.x * inv;  acc.y += v.y * inv;
            acc.z += v.z * inv;  acc.w += v.w * inv;
        }
    }

    // Reuse stage buffer: thread tid writes float4 slot tid (only slots it
    // itself consumed) -> no hazard before the barrier.
    sacc[tid] = acc;
    __syncthreads();
    if (tid < D) {
        float s = 0.f;
        #pragma unroll
        for (int ww = 0; ww < NW; ww++)
            s += ((const float*)(sacc + ww * 32))[tid];
        g_partialS[bid * D + tid] = s;
    }
    __threadfence();
    __syncthreads();
    if (tid == 0) atomicAdd(&g_cnt1, 1u);

    // ================= grid sync =================
    if (tid == 0) {
        while (*((volatile unsigned int*)&g_cnt1) != GRID) { }
        __threadfence();
    }
    __syncthreads();

    // ================= Phase 2a: rebuild S (parallel, fixed order) =================
    {
        const int col = tid & (D - 1);
        const int q   = tid >> 7;                // 0..7
        float s = 0.f;
        #pragma unroll 1
        for (int b = q; b < GRID; b += 8)
            s += g_partialS[b * D + col];
        Sq[q * D + col] = s;
    }
    __syncthreads();
    if (tid < D) {
        float t = 0.f;
        #pragma unroll
        for (int j = 0; j < 8; j++) t += Sq[j * D + tid];
        S[tid] = t;
    }
    __syncthreads();

    const float4 s4 = ((const float4*)S)[lane];

    // ================= Phase 2b: per-row loss, spread over all blocks =================
    float lsum = 0.f;
    {
        int n = w * GRID + bid;                  // N=1024 -> warps 0..6 valid
        if (n < N) {
            float4 rv = real[(size_t)n * DV + lane];
            float4 pv = pert[(size_t)n * DV + lane];
            float rr = warp_sum(dot4(rv, rv));
            float pp = warp_sum(dot4(pv, pv));
            float rp = warp_sum(dot4(rv, pv));
            float rs = warp_sum(dot4(rv, s4));
            if (lane == 0) {
                float rn  = fmaxf(sqrtf(rr), EPSN);
                float pn  = fmaxf(sqrtf(pp), EPSN);
                float pos = rp / (rn * pn) * INV_T;
                float neg = rs / rn * INV_T;
                float mx  = fmaxf(pos, neg);
                float lse = mx + logf(expf(pos - mx) + expf(neg - mx));
                lsum = lse - pos;                // -log_softmax[0]
            }
        }
    }
    if (lane == 0) wsum[w] = lsum;
    __syncthreads();

    if (tid == 0) {
        float b = 0.f;
        #pragma unroll
        for (int ww = 0; ww < NW; ww++) b += wsum[ww];
        g_partialLoss[bid] = b;
        __threadfence();
        unsigned int ret = atomicAdd(&g_cnt2, 1u);
        *islast = (ret == GRID - 1) ? 1 : 0;
    }
    __syncthreads();

    if (*islast && w == 0) {
        __threadfence();
        float v = 0.f;
        #pragma unroll
        for (int j = 0; j < 5; j++) {
            int i = lane + 32 * j;
            if (i < GRID) v += g_partialLoss[i];
        }
        v = warp_sum(v);
        if (lane == 0) {
            out[0] = v / (float)N;
            g_cnt1 = 0;
            g_cnt2 = 0;
        }
    }
}

extern "C" void kernel_launch(void* const* d_in, const int* in_sizes, int n_in,
                              void* d_out, int out_size) {
    const float4* real = (const float4*)d_in[0];
    const float4* pert = (const float4*)d_in[1];
    const float4* mem  = (const float4*)d_in[2];
    int N = in_sizes[0] / D;
    int M = in_sizes[2] / D;

    // Opt in to >48KB-capable dynamic smem. Not a stream op: creates no graph
    // node, allocates nothing, idempotent across calls -> capture-safe.
    cudaFuncSetAttribute(fused_ntxent_kernel,
                         cudaFuncAttributeMaxDynamicSharedMemorySize, 65536);

    fused_ntxent_kernel<<<GRID, T, SMEM_BYTES>>>(mem, M, real, pert, N,
                                                 (float*)d_out);
}